// round 3
// baseline (speedup 1.0000x reference)
#include <cuda_runtime.h>
#include <math_constants.h>

// Problem constants (fixed by the reference)
#define B_   32
#define S_   16
#define T_   260
#define D_   768
#define P_   256
#define TOPK 4

// Output layout (all float32, concatenated):
//   [0,          TOK)      sparse_tokens     (32*16*260*768)
//   [TOK, +MASKN)          particle_pad_mask (32*260)
//   [.., +IDXN)            padded_idx        (32*256)
//   [.., +IDXN)            valid             (32*256)
//   [last]                 active_mean
#define TOK_N   ((long long)B_ * S_ * T_ * D_)   // 102,236,160
#define MASK_N  (B_ * T_)                        // 8,320
#define IDX_N   (B_ * P_)                        // 8,192
#define OFF_MASK  (TOK_N)
#define OFF_IDX   (OFF_MASK + MASK_N)
#define OFF_VALID (OFF_IDX + IDX_N)
#define OFF_MEAN  (OFF_VALID + IDX_N)

__device__ int   g_idx[B_ * P_];
__device__ float g_counts[B_];

// ---------------------------------------------------------------------------
// Kernel 1: routing. One block per batch, 256 threads (one per particle).
// ---------------------------------------------------------------------------
__global__ void route_kernel(const float* __restrict__ z, float* __restrict__ out) {
    const int b = blockIdx.x;
    const int p = threadIdx.x;

    // scores[p] = max over S of z_obj_on[b, :, p]
    const float* zb = z + (long long)b * S_ * P_;
    float score = -CUDART_INF_F;
    #pragma unroll
    for (int s = 0; s < S_; ++s)
        score = fmaxf(score, zb[s * P_ + p]);

    __shared__ float sval[P_];
    __shared__ int   pre[P_];
    __shared__ int   sorder[P_];
    __shared__ float rv[P_];
    __shared__ int   ri[P_];

    sval[p] = score;
    int act = (score > 0.5f) ? 1 : 0;

    // inclusive scan of act
    pre[p] = act;
    __syncthreads();
    #pragma unroll
    for (int off = 1; off < P_; off <<= 1) {
        int v = (p >= off) ? pre[p - off] : 0;
        __syncthreads();
        pre[p] += v;
        __syncthreads();
    }
    int cnt = pre[P_ - 1];

    if (cnt == 0) {
        // fallback: top-4 scores (ties -> lowest index, matching lax.top_k)
        int is_fb = 0;
        #pragma unroll
        for (int k = 0; k < TOPK; ++k) {
            rv[p] = sval[p];
            ri[p] = p;
            __syncthreads();
            #pragma unroll
            for (int off = P_ / 2; off > 0; off >>= 1) {
                if (p < off) {
                    float ov = rv[p + off]; int oi = ri[p + off];
                    if (ov > rv[p] || (ov == rv[p] && oi < ri[p])) { rv[p] = ov; ri[p] = oi; }
                }
                __syncthreads();
            }
            int win = ri[0];
            __syncthreads();
            if (p == win) { is_fb = 1; sval[p] = -CUDART_INF_F; }
            __syncthreads();
        }
        act = is_fb;
        // rescan
        pre[p] = act;
        __syncthreads();
        #pragma unroll
        for (int off = 1; off < P_; off <<= 1) {
            int v = (p >= off) ? pre[p - off] : 0;
            __syncthreads();
            pre[p] += v;
            __syncthreads();
        }
        cnt = pre[P_ - 1];
    }

    // stable partition: active indices ascending, then inactive ascending
    int rank = act ? (pre[p] - 1) : (cnt + (p - pre[p]));
    sorder[rank] = p;
    __syncthreads();

    int v = (p < cnt) ? 1 : 0;
    int pidx = v ? sorder[p] : 0;

    g_idx[b * P_ + p] = pidx;

    // small outputs
    out[OFF_MASK  + (long long)b * T_ + p] = v ? 1.0f : 0.0f;
    if (p < (T_ - P_))
        out[OFF_MASK + (long long)b * T_ + P_ + p] = 1.0f;  // tail always valid
    out[OFF_IDX   + (long long)b * P_ + p] = (float)pidx;
    out[OFF_VALID + (long long)b * P_ + p] = v ? 1.0f : 0.0f;
    if (p == 0)
        g_counts[b] = (float)cnt;
}

// ---------------------------------------------------------------------------
// Kernel 2: active_mean (exact: counts are small integers, sum <= 8192)
// ---------------------------------------------------------------------------
__global__ void mean_kernel(float* __restrict__ out) {
    if (threadIdx.x == 0) {
        float t = 0.0f;
        #pragma unroll
        for (int i = 0; i < B_; ++i) t += g_counts[i];
        out[OFF_MEAN] = t / (float)B_;
    }
}

// ---------------------------------------------------------------------------
// Kernel 3: the big gather. Each block copies ROWS_PER_BLK output rows.
// A row is 768 floats = 192 float4 = 3072 B, fully coalesced.
// ---------------------------------------------------------------------------
#define ROWS_PER_BLK 2
#define GATHER_THREADS (ROWS_PER_BLK * (D_ / 4))   // 384

__global__ __launch_bounds__(GATHER_THREADS)
void gather_kernel(const float* __restrict__ tok, float* __restrict__ out) {
    const int lane_row = threadIdx.x / (D_ / 4);   // 0..ROWS_PER_BLK-1
    const int lane     = threadIdx.x % (D_ / 4);   // 0..191

    const int row = blockIdx.x * ROWS_PER_BLK + lane_row;   // 0 .. B*S*T-1
    const int t   = row % T_;
    const int bs  = row / T_;            // b*S + s
    const int b   = bs >> 4;             // S_ == 16

    const int src_t = (t < P_) ? g_idx[b * P_ + t] : t;

    const float4* __restrict__ src =
        reinterpret_cast<const float4*>(tok + ((long long)bs * T_ + src_t) * D_);
    float4* __restrict__ dst =
        reinterpret_cast<float4*>(out + (long long)row * D_);

    dst[lane] = src[lane];
}

// ---------------------------------------------------------------------------
extern "C" void kernel_launch(void* const* d_in, const int* in_sizes, int n_in,
                              void* d_out, int out_size) {
    // metadata order: tokens, z_obj_on — but pick by size defensively
    const float* tokens = (const float*)d_in[0];
    const float* z      = (const float*)d_in[1];
    if (n_in >= 2 && in_sizes[0] == B_ * S_ * P_) {
        tokens = (const float*)d_in[1];
        z      = (const float*)d_in[0];
    }
    float* out = (float*)d_out;

    route_kernel<<<B_, P_>>>(z, out);
    mean_kernel<<<1, 32>>>(out);
    // B*S*T = 133,120 rows, ROWS_PER_BLK per block
    gather_kernel<<<(B_ * S_ * T_) / ROWS_PER_BLK, GATHER_THREADS>>>(tokens, out);
}

// round 5
// speedup vs baseline: 1.0947x; 1.0947x over previous
#include <cuda_runtime.h>
#include <math_constants.h>

// Problem constants (fixed by the reference)
#define B_   32
#define S_   16
#define T_   260
#define D_   768
#define P_   256
#define TOPK 4

// Output layout (all float32, concatenated):
//   [0,          TOK)      sparse_tokens     (32*16*260*768)
//   [TOK, +MASKN)          particle_pad_mask (32*260)
//   [.., +IDXN)            padded_idx        (32*256)
//   [.., +IDXN)            valid             (32*256)
//   [last]                 active_mean
#define TOK_N   ((long long)B_ * S_ * T_ * D_)   // 102,236,160
#define MASK_N  (B_ * T_)                        // 8,320
#define IDX_N   (B_ * P_)                        // 8,192
#define OFF_MASK  (TOK_N)
#define OFF_IDX   (OFF_MASK + MASK_N)
#define OFF_VALID (OFF_IDX + IDX_N)
#define OFF_MEAN  (OFF_VALID + IDX_N)

__device__ int   g_idx[B_ * P_];
__device__ float g_counts[B_];

// ---------------------------------------------------------------------------
// Kernel 1: routing. One block per batch, 256 threads (one per particle).
// Ballot-based scan instead of shared-memory Hillis-Steele.
// ---------------------------------------------------------------------------
__global__ void route_kernel(const float* __restrict__ z, float* __restrict__ out) {
    const int b = blockIdx.x;
    const int p = threadIdx.x;
    const int lane = p & 31;
    const int w    = p >> 5;          // warp id, 0..7

    // scores[p] = max over S of z_obj_on[b, :, p]
    const float* zb = z + (long long)b * S_ * P_;
    float score = -CUDART_INF_F;
    #pragma unroll
    for (int s = 0; s < S_; ++s)
        score = fmaxf(score, zb[s * P_ + p]);

    __shared__ float sval[P_];
    __shared__ int   sorder[P_];
    __shared__ int   wsum[P_ / 32];
    __shared__ float rv[P_];
    __shared__ int   ri[P_];

    sval[p] = score;
    int act = (score > 0.5f) ? 1 : 0;

    // warp-level inclusive scan of act via ballot
    unsigned m = __ballot_sync(0xffffffffu, act);
    int wpre = __popc(m & ((lane == 31) ? 0xffffffffu : ((1u << (lane + 1)) - 1u)));
    if (lane == 31) wsum[w] = wpre;
    __syncthreads();
    int off = 0;
    #pragma unroll
    for (int i = 0; i < P_ / 32; ++i) off += (i < w) ? wsum[i] : 0;
    int pre = off + wpre;             // inclusive prefix over block
    int cnt = 0;
    #pragma unroll
    for (int i = 0; i < P_ / 32; ++i) cnt += wsum[i];

    if (cnt == 0) {
        // fallback: top-4 scores (ties -> lowest index, matching lax.top_k)
        int is_fb = 0;
        #pragma unroll
        for (int k = 0; k < TOPK; ++k) {
            rv[p] = sval[p];
            ri[p] = p;
            __syncthreads();
            #pragma unroll
            for (int o = P_ / 2; o > 0; o >>= 1) {
                if (p < o) {
                    float ov = rv[p + o]; int oi = ri[p + o];
                    if (ov > rv[p] || (ov == rv[p] && oi < ri[p])) { rv[p] = ov; ri[p] = oi; }
                }
                __syncthreads();
            }
            int win = ri[0];
            __syncthreads();
            if (p == win) { is_fb = 1; sval[p] = -CUDART_INF_F; }
            __syncthreads();
        }
        act = is_fb;
        // rescan
        m = __ballot_sync(0xffffffffu, act);
        wpre = __popc(m & ((lane == 31) ? 0xffffffffu : ((1u << (lane + 1)) - 1u)));
        if (lane == 31) wsum[w] = wpre;
        __syncthreads();
        off = 0;
        #pragma unroll
        for (int i = 0; i < P_ / 32; ++i) off += (i < w) ? wsum[i] : 0;
        pre = off + wpre;
        cnt = 0;
        #pragma unroll
        for (int i = 0; i < P_ / 32; ++i) cnt += wsum[i];
    }

    // stable partition: active indices ascending, then inactive ascending
    int rank = act ? (pre - 1) : (cnt + (p - pre));
    sorder[rank] = p;
    __syncthreads();

    int v = (p < cnt) ? 1 : 0;
    int pidx = v ? sorder[p] : 0;

    g_idx[b * P_ + p] = pidx;

    // small outputs
    out[OFF_MASK  + (long long)b * T_ + p] = v ? 1.0f : 0.0f;
    if (p < (T_ - P_))
        out[OFF_MASK + (long long)b * T_ + P_ + p] = 1.0f;  // tail always valid
    out[OFF_IDX   + (long long)b * P_ + p] = (float)pidx;
    out[OFF_VALID + (long long)b * P_ + p] = v ? 1.0f : 0.0f;
    if (p == 0)
        g_counts[b] = (float)cnt;
}

// ---------------------------------------------------------------------------
// Kernel 2: active_mean (exact: counts are small integers, sum <= 8192)
// ---------------------------------------------------------------------------
__global__ void mean_kernel(float* __restrict__ out) {
    if (threadIdx.x == 0) {
        float t = 0.0f;
        #pragma unroll
        for (int i = 0; i < B_; ++i) t += g_counts[i];
        out[OFF_MEAN] = t / (float)B_;
    }
}

// ---------------------------------------------------------------------------
// Kernel 3: the big gather. 192 threads/block, RPB rows per block.
// Each thread front-batches RPB independent LDG.128 (MLP=RPB), then stores
// with streaming hint (__stcs) so the write stream doesn't evict the hot
// row-0 tiles from L2.
// ---------------------------------------------------------------------------
#define RPB 4
#define LANES (D_ / 4)   // 192 float4 per row

__global__ __launch_bounds__(LANES)
void gather_kernel(const float* __restrict__ tok, float* __restrict__ out) {
    const int lane = threadIdx.x;                 // 0..191
    const int row0 = blockIdx.x * RPB;            // 0 .. B*S*T-1

    const float4* src[RPB];
    #pragma unroll
    for (int r = 0; r < RPB; ++r) {
        const int row = row0 + r;
        const int t   = row % T_;
        const int bs  = row / T_;                 // b*S + s
        const int b   = bs >> 4;                  // S_ == 16
        const int st  = (t < P_) ? g_idx[b * P_ + t] : t;
        src[r] = reinterpret_cast<const float4*>(tok + ((long long)bs * T_ + st) * D_);
    }

    float4 v[RPB];
    #pragma unroll
    for (int r = 0; r < RPB; ++r)
        v[r] = src[r][lane];                      // RPB independent loads in flight

    #pragma unroll
    for (int r = 0; r < RPB; ++r) {
        float4* dst = reinterpret_cast<float4*>(out + (long long)(row0 + r) * D_);
        __stcs(&dst[lane], v[r]);                 // streaming store
    }
}

// ---------------------------------------------------------------------------
extern "C" void kernel_launch(void* const* d_in, const int* in_sizes, int n_in,
                              void* d_out, int out_size) {
    // metadata order: tokens, z_obj_on — but pick by size defensively
    const float* tokens = (const float*)d_in[0];
    const float* z      = (const float*)d_in[1];
    if (n_in >= 2 && in_sizes[0] == B_ * S_ * P_) {
        tokens = (const float*)d_in[1];
        z      = (const float*)d_in[0];
    }
    float* out = (float*)d_out;

    route_kernel<<<B_, P_>>>(z, out);
    mean_kernel<<<1, 32>>>(out);
    // B*S*T = 133,120 rows, RPB per block -> 33,280 blocks
    gather_kernel<<<(B_ * S_ * T_) / RPB, LANES>>>(tokens, out);
}

// round 6
// speedup vs baseline: 1.0949x; 1.0003x over previous
#include <cuda_runtime.h>
#include <math_constants.h>

// Problem constants (fixed by the reference)
#define B_   32
#define S_   16
#define T_   260
#define D_   768
#define P_   256
#define TOPK 4

// Output layout (all float32, concatenated):
//   [0,          TOK)      sparse_tokens     (32*16*260*768)
//   [TOK, +MASKN)          particle_pad_mask (32*260)
//   [.., +IDXN)            padded_idx        (32*256)
//   [.., +IDXN)            valid             (32*256)
//   [last]                 active_mean
#define TOK_N   ((long long)B_ * S_ * T_ * D_)   // 102,236,160
#define MASK_N  (B_ * T_)                        // 8,320
#define IDX_N   (B_ * P_)                        // 8,192
#define OFF_MASK  (TOK_N)
#define OFF_IDX   (OFF_MASK + MASK_N)
#define OFF_VALID (OFF_IDX + IDX_N)
#define OFF_MEAN  (OFF_VALID + IDX_N)

__device__ int   g_idx[B_ * P_];
__device__ float g_counts[B_];

// ---------------------------------------------------------------------------
// Kernel 1: routing. One block per batch, 256 threads (one per particle).
// ---------------------------------------------------------------------------
__global__ void route_kernel(const float* __restrict__ z, float* __restrict__ out) {
    const int b = blockIdx.x;
    const int p = threadIdx.x;
    const int lane = p & 31;
    const int w    = p >> 5;          // warp id, 0..7

    // scores[p] = max over S of z_obj_on[b, :, p]
    const float* zb = z + (long long)b * S_ * P_;
    float score = -CUDART_INF_F;
    #pragma unroll
    for (int s = 0; s < S_; ++s)
        score = fmaxf(score, zb[s * P_ + p]);

    __shared__ float sval[P_];
    __shared__ int   sorder[P_];
    __shared__ int   wsum[P_ / 32];
    __shared__ float rv[P_];
    __shared__ int   ri[P_];

    sval[p] = score;
    int act = (score > 0.5f) ? 1 : 0;

    // warp-level inclusive scan of act via ballot
    unsigned m = __ballot_sync(0xffffffffu, act);
    int wpre = __popc(m & ((lane == 31) ? 0xffffffffu : ((1u << (lane + 1)) - 1u)));
    if (lane == 31) wsum[w] = wpre;
    __syncthreads();
    int off = 0;
    #pragma unroll
    for (int i = 0; i < P_ / 32; ++i) off += (i < w) ? wsum[i] : 0;
    int pre = off + wpre;             // inclusive prefix over block
    int cnt = 0;
    #pragma unroll
    for (int i = 0; i < P_ / 32; ++i) cnt += wsum[i];

    if (cnt == 0) {
        // fallback: top-4 scores (ties -> lowest index, matching lax.top_k)
        int is_fb = 0;
        #pragma unroll
        for (int k = 0; k < TOPK; ++k) {
            rv[p] = sval[p];
            ri[p] = p;
            __syncthreads();
            #pragma unroll
            for (int o = P_ / 2; o > 0; o >>= 1) {
                if (p < o) {
                    float ov = rv[p + o]; int oi = ri[p + o];
                    if (ov > rv[p] || (ov == rv[p] && oi < ri[p])) { rv[p] = ov; ri[p] = oi; }
                }
                __syncthreads();
            }
            int win = ri[0];
            __syncthreads();
            if (p == win) { is_fb = 1; sval[p] = -CUDART_INF_F; }
            __syncthreads();
        }
        act = is_fb;
        // rescan
        m = __ballot_sync(0xffffffffu, act);
        wpre = __popc(m & ((lane == 31) ? 0xffffffffu : ((1u << (lane + 1)) - 1u)));
        if (lane == 31) wsum[w] = wpre;
        __syncthreads();
        off = 0;
        #pragma unroll
        for (int i = 0; i < P_ / 32; ++i) off += (i < w) ? wsum[i] : 0;
        pre = off + wpre;
        cnt = 0;
        #pragma unroll
        for (int i = 0; i < P_ / 32; ++i) cnt += wsum[i];
    }

    // stable partition: active indices ascending, then inactive ascending
    int rank = act ? (pre - 1) : (cnt + (p - pre));
    sorder[rank] = p;
    __syncthreads();

    int v = (p < cnt) ? 1 : 0;
    int pidx = v ? sorder[p] : 0;

    g_idx[b * P_ + p] = pidx;

    // small outputs
    out[OFF_MASK  + (long long)b * T_ + p] = v ? 1.0f : 0.0f;
    if (p < (T_ - P_))
        out[OFF_MASK + (long long)b * T_ + P_ + p] = 1.0f;  // tail always valid
    out[OFF_IDX   + (long long)b * P_ + p] = (float)pidx;
    out[OFF_VALID + (long long)b * P_ + p] = v ? 1.0f : 0.0f;
    if (p == 0)
        g_counts[b] = (float)cnt;
}

// ---------------------------------------------------------------------------
// Kernel 2: the big gather. 192 threads/block, RPB rows per block.
// Each thread front-batches RPB independent LDG.128 (MLP=RPB), then stores
// with streaming hint (__stcs). Block 0 also computes active_mean (g_counts
// is ready because gather launches after route on the same stream; the sum
// of <=8192 small integers is exact in fp32, /32 is a power-of-2 scale).
// ---------------------------------------------------------------------------
#define RPB 8
#define LANES (D_ / 4)   // 192 float4 per row

__global__ __launch_bounds__(LANES)
void gather_kernel(const float* __restrict__ tok, float* __restrict__ out) {
    const int lane = threadIdx.x;                 // 0..191
    const int row0 = blockIdx.x * RPB;            // 0 .. B*S*T-1

    if (blockIdx.x == 0 && lane == 0) {
        float t = 0.0f;
        #pragma unroll
        for (int i = 0; i < B_; ++i) t += g_counts[i];
        out[OFF_MEAN] = t / (float)B_;
    }

    const float4* src[RPB];
    #pragma unroll
    for (int r = 0; r < RPB; ++r) {
        const int row = row0 + r;
        const int t   = row % T_;
        const int bs  = row / T_;                 // b*S + s
        const int b   = bs >> 4;                  // S_ == 16
        const int st  = (t < P_) ? g_idx[b * P_ + t] : t;
        src[r] = reinterpret_cast<const float4*>(tok + ((long long)bs * T_ + st) * D_);
    }

    float4 v[RPB];
    #pragma unroll
    for (int r = 0; r < RPB; ++r)
        v[r] = src[r][lane];                      // RPB independent loads in flight

    #pragma unroll
    for (int r = 0; r < RPB; ++r) {
        float4* dst = reinterpret_cast<float4*>(out + (long long)(row0 + r) * D_);
        __stcs(&dst[lane], v[r]);                 // streaming store
    }
}

// ---------------------------------------------------------------------------
extern "C" void kernel_launch(void* const* d_in, const int* in_sizes, int n_in,
                              void* d_out, int out_size) {
    // metadata order: tokens, z_obj_on — but pick by size defensively
    const float* tokens = (const float*)d_in[0];
    const float* z      = (const float*)d_in[1];
    if (n_in >= 2 && in_sizes[0] == B_ * S_ * P_) {
        tokens = (const float*)d_in[1];
        z      = (const float*)d_in[0];
    }
    float* out = (float*)d_out;

    route_kernel<<<B_, P_>>>(z, out);
    // B*S*T = 133,120 rows, RPB per block -> 16,640 blocks
    gather_kernel<<<(B_ * S_ * T_) / RPB, LANES>>>(tokens, out);
}

// round 7
// speedup vs baseline: 1.1143x; 1.0177x over previous
#include <cuda_runtime.h>
#include <math_constants.h>

// Problem constants (fixed by the reference)
#define B_   32
#define S_   16
#define T_   260
#define D_   768
#define P_   256
#define TOPK 4

#define TOK_N   ((long long)B_ * S_ * T_ * D_)   // 102,236,160
#define MASK_N  (B_ * T_)                        // 8,320
#define IDX_N   (B_ * P_)                        // 8,192
#define OFF_MASK  (TOK_N)
#define OFF_IDX   (OFF_MASK + MASK_N)
#define OFF_VALID (OFF_IDX + IDX_N)
#define OFF_MEAN  (OFF_VALID + IDX_N)

__device__ int   g_idx[B_ * P_];
__device__ float g_counts[B_];

// ---------------------------------------------------------------------------
// Routing for one batch (256 threads). Same logic as before.
// ---------------------------------------------------------------------------
__device__ __forceinline__ void do_route(int b, const float* __restrict__ z,
                                         float* __restrict__ out) {
    const int p = threadIdx.x;
    const int lane = p & 31;
    const int w    = p >> 5;

    const float* zb = z + (long long)b * S_ * P_;
    float score = -CUDART_INF_F;
    #pragma unroll
    for (int s = 0; s < S_; ++s)
        score = fmaxf(score, zb[s * P_ + p]);

    __shared__ float sval[P_];
    __shared__ int   sorder[P_];
    __shared__ int   wsum[P_ / 32];
    __shared__ float rv[P_];
    __shared__ int   ri[P_];

    sval[p] = score;
    int act = (score > 0.5f) ? 1 : 0;

    unsigned m = __ballot_sync(0xffffffffu, act);
    int wpre = __popc(m & ((lane == 31) ? 0xffffffffu : ((1u << (lane + 1)) - 1u)));
    if (lane == 31) wsum[w] = wpre;
    __syncthreads();
    int off = 0;
    #pragma unroll
    for (int i = 0; i < P_ / 32; ++i) off += (i < w) ? wsum[i] : 0;
    int pre = off + wpre;
    int cnt = 0;
    #pragma unroll
    for (int i = 0; i < P_ / 32; ++i) cnt += wsum[i];

    if (cnt == 0) {
        // fallback: top-4 scores (ties -> lowest index, matching lax.top_k)
        int is_fb = 0;
        #pragma unroll
        for (int k = 0; k < TOPK; ++k) {
            rv[p] = sval[p];
            ri[p] = p;
            __syncthreads();
            #pragma unroll
            for (int o = P_ / 2; o > 0; o >>= 1) {
                if (p < o) {
                    float ov = rv[p + o]; int oi = ri[p + o];
                    if (ov > rv[p] || (ov == rv[p] && oi < ri[p])) { rv[p] = ov; ri[p] = oi; }
                }
                __syncthreads();
            }
            int win = ri[0];
            __syncthreads();
            if (p == win) { is_fb = 1; sval[p] = -CUDART_INF_F; }
            __syncthreads();
        }
        act = is_fb;
        m = __ballot_sync(0xffffffffu, act);
        wpre = __popc(m & ((lane == 31) ? 0xffffffffu : ((1u << (lane + 1)) - 1u)));
        if (lane == 31) wsum[w] = wpre;
        __syncthreads();
        off = 0;
        #pragma unroll
        for (int i = 0; i < P_ / 32; ++i) off += (i < w) ? wsum[i] : 0;
        pre = off + wpre;
        cnt = 0;
        #pragma unroll
        for (int i = 0; i < P_ / 32; ++i) cnt += wsum[i];
    }

    // stable partition: active indices ascending, then inactive ascending
    int rank = act ? (pre - 1) : (cnt + (p - pre));
    sorder[rank] = p;
    __syncthreads();

    int v = (p < cnt) ? 1 : 0;
    int pidx = v ? sorder[p] : 0;

    g_idx[b * P_ + p] = pidx;

    out[OFF_MASK  + (long long)b * T_ + p] = v ? 1.0f : 0.0f;
    if (p < (T_ - P_))
        out[OFF_MASK + (long long)b * T_ + P_ + p] = 1.0f;  // tail always valid
    out[OFF_IDX   + (long long)b * P_ + p] = (float)pidx;
    out[OFF_VALID + (long long)b * P_ + p] = v ? 1.0f : 0.0f;
    if (p == 0)
        g_counts[b] = (float)cnt;
}

// ---------------------------------------------------------------------------
// Kernel A: fused route + identity memcpy.
//   blocks 0..31          -> routing for batch b=blockIdx.x (runs in wave 1,
//                            hidden under the copy)
//   blocks 32..32+NCOPY-1 -> flat float4 memcpy of all tokens. This is the
//                            correct final result for every row with
//                            g_idx[t]==t (the overwhelmingly common case) and
//                            for the tail rows; kernel B fixes the rest.
// ---------------------------------------------------------------------------
#define CPY_THREADS 256
#define V_PER_THR   8
#define F4_TOTAL    (TOK_N / 4)                          // 25,559,040
#define F4_PER_BLK  (CPY_THREADS * V_PER_THR)            // 2048
#define NCOPY       ((int)(F4_TOTAL / F4_PER_BLK))       // 12,480 (exact)

__global__ __launch_bounds__(CPY_THREADS)
void fused_kernel(const float* __restrict__ tok, const float* __restrict__ z,
                  float* __restrict__ out) {
    if (blockIdx.x < B_) {
        do_route(blockIdx.x, z, out);
        return;
    }
    const long long base = (long long)(blockIdx.x - B_) * F4_PER_BLK + threadIdx.x;
    const float4* __restrict__ s4 = reinterpret_cast<const float4*>(tok);
    float4* __restrict__ d4 = reinterpret_cast<float4*>(out);

    float4 v[V_PER_THR];
    #pragma unroll
    for (int k = 0; k < V_PER_THR; ++k)
        v[k] = __ldcs(&s4[base + (long long)k * CPY_THREADS]);
    #pragma unroll
    for (int k = 0; k < V_PER_THR; ++k)
        __stcs(&d4[base + (long long)k * CPY_THREADS], v[k]);
}

// ---------------------------------------------------------------------------
// Kernel B: fixup rows where g_idx[t] != t, plus active_mean.
// One block per batch. Expected mismatch count for this input: ~0.
// ---------------------------------------------------------------------------
__global__ __launch_bounds__(256)
void fixup_kernel(const float* __restrict__ tok, float* __restrict__ out) {
    const int b   = blockIdx.x;
    const int tid = threadIdx.x;

    if (b == 0 && tid == 0) {
        float t = 0.0f;
        #pragma unroll
        for (int i = 0; i < B_; ++i) t += g_counts[i];
        out[OFF_MEAN] = t / (float)B_;
    }

    __shared__ int list[P_];
    __shared__ int nmis;
    if (tid == 0) nmis = 0;
    __syncthreads();

    if (tid < P_) {
        int idx = g_idx[b * P_ + tid];
        if (idx != tid) {
            int k = atomicAdd(&nmis, 1);
            list[k] = tid;
        }
    }
    __syncthreads();

    const float4* __restrict__ s4 = reinterpret_cast<const float4*>(tok);
    float4* __restrict__ d4 = reinterpret_cast<float4*>(out);
    const int LPR = D_ / 4;   // 192 float4 per row

    for (int m = 0; m < nmis; ++m) {
        const int t  = list[m];
        const int st = g_idx[b * P_ + t];
        for (int i = tid; i < S_ * LPR; i += 256) {
            const int s    = i / LPR;
            const int lane = i % LPR;
            const long long bs = (long long)b * S_ + s;
            d4[(bs * T_ + t)  * LPR + lane] = s4[(bs * T_ + st) * LPR + lane];
        }
    }
}

// ---------------------------------------------------------------------------
extern "C" void kernel_launch(void* const* d_in, const int* in_sizes, int n_in,
                              void* d_out, int out_size) {
    const float* tokens = (const float*)d_in[0];
    const float* z      = (const float*)d_in[1];
    if (n_in >= 2 && in_sizes[0] == B_ * S_ * P_) {
        tokens = (const float*)d_in[1];
        z      = (const float*)d_in[0];
    }
    float* out = (float*)d_out;

    fused_kernel<<<B_ + NCOPY, CPY_THREADS>>>(tokens, z, out);
    fixup_kernel<<<B_, 256>>>(tokens, out);
}